// round 7
// baseline (speedup 1.0000x reference)
#include <cuda_runtime.h>
#include <cuda_bf16.h>
#include <cuda_fp16.h>
#include <mma.h>
#include <math.h>
#include <stdint.h>

using namespace nvcuda;

#define BATCH 2
#define SEQ   2048
#define DM    1024
#define NH    16
#define HD    64
#define MTOT  (BATCH*SEQ)
#define KC    64
#define LDK   72
#define STG   68          // fp32 staging stride (64 + 4)

static const size_t OUT_ELEMS  = (size_t)BATCH * SEQ * DM;
static const size_t ATTN_ELEMS = (size_t)BATCH * NH * SEQ * SEQ;

// ---------------------------------------------------------------------------
// Device scratch
// ---------------------------------------------------------------------------
__device__ __nv_bfloat16 g_xq_hi[MTOT*DM], g_xq_lo[MTOT*DM];
__device__ __nv_bfloat16 g_xk_hi[MTOT*DM], g_xk_lo[MTOT*DM];
__device__ __nv_bfloat16 g_xv_hi[MTOT*DM], g_xv_lo[MTOT*DM];
__device__ __nv_bfloat16 g_wq_hi[DM*DM], g_wq_lo[DM*DM];
__device__ __nv_bfloat16 g_wk_hi[DM*DM], g_wk_lo[DM*DM];
__device__ __nv_bfloat16 g_wv_hi[DM*DM], g_wv_lo[DM*DM];
__device__ __nv_bfloat16 g_wo_hi[DM*DM], g_wo_lo[DM*DM];
__device__ __nv_bfloat16 g_q_hi[BATCH*NH*SEQ*HD], g_q_lo[BATCH*NH*SEQ*HD];
__device__ __nv_bfloat16 g_k_hi[BATCH*NH*SEQ*HD], g_k_lo[BATCH*NH*SEQ*HD];
__device__ __nv_bfloat16 g_v_hi[BATCH*NH*SEQ*HD], g_v_lo[BATCH*NH*SEQ*HD];
__device__ __nv_bfloat16 g_ctx_hi[MTOT*DM], g_ctx_lo[MTOT*DM];
__device__ __half g_e[(size_t)BATCH*NH*SEQ*SEQ];            // fp16 exp strip buffer
__device__ float g_attn_scratch[(size_t)BATCH*NH*SEQ*SEQ];  // fallback attn

// ---------------------------------------------------------------------------
// Helpers
// ---------------------------------------------------------------------------
__device__ __forceinline__ void cp16(void* dst, const void* src) {
    asm volatile("cp.async.cg.shared.global [%0], [%1], 16;"
                 :: "r"((uint32_t)__cvta_generic_to_shared(dst)), "l"(src));
}
__device__ __forceinline__ void cp_commit() {
    asm volatile("cp.async.commit_group;");
}
__device__ __forceinline__ uint32_t bfpack(float a, float b) {
    __nv_bfloat162 t(__float2bfloat16(a), __float2bfloat16(b));
    return *(uint32_t*)&t;
}

__global__ void __launch_bounds__(256)
convert_split(const float4* __restrict__ src, uint2* __restrict__ hi,
              uint2* __restrict__ lo, int n4)
{
    int i = blockIdx.x * 256 + threadIdx.x;
    if (i >= n4) return;
    float4 v = src[i];
    __nv_bfloat16 hx = __float2bfloat16(v.x), hy = __float2bfloat16(v.y);
    __nv_bfloat16 hz = __float2bfloat16(v.z), hw = __float2bfloat16(v.w);
    __nv_bfloat162 h01(hx, hy), h23(hz, hw);
    hi[i] = make_uint2(*(uint32_t*)&h01, *(uint32_t*)&h23);
    lo[i] = make_uint2(bfpack(v.x - __bfloat162float(hx), v.y - __bfloat162float(hy)),
                       bfpack(v.z - __bfloat162float(hz), v.w - __bfloat162float(hw)));
}

// ---------------------------------------------------------------------------
// HMMA GEMM (unchanged from R6)
// ---------------------------------------------------------------------------
struct GemmPtrs {
    const __nv_bfloat16 *Ahi[3], *Alo[3], *Whi[3], *Wlo[3];
    const float* bias[3];
    float* outF[3];
    __nv_bfloat16 *outHi[3], *outLo[3];
};

#define GTILE (128*LDK)
#define GSTAGE (4*GTILE)

template<int MODE>
__global__ void __launch_bounds__(256)
gemm_bf16(GemmPtrs P, int M, int N, int K)
{
    extern __shared__ __align__(16) __nv_bfloat16 sm[];
    const int z = (MODE == 0) ? blockIdx.z : 0;
    const __nv_bfloat16* Ahi = P.Ahi[z];
    const __nv_bfloat16* Alo = P.Alo[z];
    const __nv_bfloat16* Whi = P.Whi[z];
    const __nv_bfloat16* Wlo = P.Wlo[z];
    const float* bias = P.bias[z];

    const int tid = threadIdx.x;
    const int wid = tid >> 5;
    const int lane = tid & 31;
    const int wr = wid & 3;
    const int wc = wid >> 2;
    const int m0 = blockIdx.y * 128;
    const int n0 = blockIdx.x * 128;

    wmma::fragment<wmma::accumulator, 16, 16, 16, float> acc[2][4];
#pragma unroll
    for (int i = 0; i < 2; i++)
#pragma unroll
        for (int j = 0; j < 4; j++) wmma::fill_fragment(acc[i][j], 0.f);

    const int NC = K / KC;

    auto stage_copy = [&](int c, int s) {
        const int k0 = c * KC;
        __nv_bfloat16* base = sm + s * GSTAGE;
#pragma unroll
        for (int t = 0; t < 4; t++) {
            int chunk = tid + t * 256;
            int row  = chunk >> 3;
            int coff = (chunk & 7) * 8;
            cp16(base + 0*GTILE + row * LDK + coff, Ahi + (size_t)(m0 + row) * K + k0 + coff);
            cp16(base + 1*GTILE + row * LDK + coff, Alo + (size_t)(m0 + row) * K + k0 + coff);
            cp16(base + 2*GTILE + row * LDK + coff, Whi + (size_t)(n0 + row) * K + k0 + coff);
            cp16(base + 3*GTILE + row * LDK + coff, Wlo + (size_t)(n0 + row) * K + k0 + coff);
        }
        cp_commit();
    };

    stage_copy(0, 0);

    for (int c = 0; c < NC; c++) {
        if (c + 1 < NC) stage_copy(c + 1, (c + 1) & 1);
        if (c + 1 < NC) asm volatile("cp.async.wait_group 1;");
        else            asm volatile("cp.async.wait_group 0;");
        __syncthreads();

        const __nv_bfloat16* base = sm + (c & 1) * GSTAGE;
        const __nv_bfloat16* sAhi = base + 0*GTILE;
        const __nv_bfloat16* sAlo = base + 1*GTILE;
        const __nv_bfloat16* sWhi = base + 2*GTILE;
        const __nv_bfloat16* sWlo = base + 3*GTILE;

#pragma unroll
        for (int kk = 0; kk < KC; kk += 16) {
            wmma::fragment<wmma::matrix_a, 16, 16, 16, __nv_bfloat16, wmma::row_major> aHi[2], aLo[2];
            wmma::fragment<wmma::matrix_b, 16, 16, 16, __nv_bfloat16, wmma::col_major> bHi[4], bLo[4];
#pragma unroll
            for (int i = 0; i < 2; i++) {
                wmma::load_matrix_sync(aHi[i], &sAhi[(wr * 32 + i * 16) * LDK + kk], LDK);
                wmma::load_matrix_sync(aLo[i], &sAlo[(wr * 32 + i * 16) * LDK + kk], LDK);
            }
#pragma unroll
            for (int j = 0; j < 4; j++) {
                wmma::load_matrix_sync(bHi[j], &sWhi[(wc * 64 + j * 16) * LDK + kk], LDK);
                wmma::load_matrix_sync(bLo[j], &sWlo[(wc * 64 + j * 16) * LDK + kk], LDK);
            }
#pragma unroll
            for (int i = 0; i < 2; i++)
#pragma unroll
                for (int j = 0; j < 4; j++) {
                    wmma::mma_sync(acc[i][j], aHi[i], bHi[j], acc[i][j]);
                    wmma::mma_sync(acc[i][j], aHi[i], bLo[j], acc[i][j]);
                    wmma::mma_sync(acc[i][j], aLo[i], bHi[j], acc[i][j]);
                }
        }
        __syncthreads();
    }

    float* scratch = (float*)sm;
    float* ws = scratch + wid * 16 * 20;
    const int er = lane >> 1;
    const int ec = (lane & 1) * 8;

#pragma unroll
    for (int i = 0; i < 2; i++)
#pragma unroll
        for (int j = 0; j < 4; j++) {
            wmma::store_matrix_sync(ws, acc[i][j], 20, wmma::mem_row_major);
            __syncwarp();
            int grow = m0 + wr * 32 + i * 16 + er;
            int col  = n0 + wc * 64 + j * 16 + ec;
            float4 b0 = *(const float4*)&bias[col];
            float4 b1 = *(const float4*)&bias[col + 4];
            float vv[8];
#pragma unroll
            for (int e = 0; e < 4; e++) vv[e]     = ws[er * 20 + ec + e]     + (&b0.x)[e];
#pragma unroll
            for (int e = 0; e < 4; e++) vv[e + 4] = ws[er * 20 + ec + 4 + e] + (&b1.x)[e];

            if (MODE == 0) {
                int b  = grow >> 11;
                int s  = grow & (SEQ - 1);
                int hh = col >> 6;
                int dd = col & (HD - 1);
                size_t off = (((size_t)(b * NH + hh)) * SEQ + s) * HD + dd;
                uint4 uh, ul;
                __nv_bfloat16 h[8];
#pragma unroll
                for (int e = 0; e < 8; e++) h[e] = __float2bfloat16(vv[e]);
                __nv_bfloat162 p0(h[0],h[1]), p1(h[2],h[3]), p2(h[4],h[5]), p3(h[6],h[7]);
                uh = make_uint4(*(uint32_t*)&p0, *(uint32_t*)&p1, *(uint32_t*)&p2, *(uint32_t*)&p3);
                ul.x = bfpack(vv[0]-__bfloat162float(h[0]), vv[1]-__bfloat162float(h[1]));
                ul.y = bfpack(vv[2]-__bfloat162float(h[2]), vv[3]-__bfloat162float(h[3]));
                ul.z = bfpack(vv[4]-__bfloat162float(h[4]), vv[5]-__bfloat162float(h[5]));
                ul.w = bfpack(vv[6]-__bfloat162float(h[6]), vv[7]-__bfloat162float(h[7]));
                *(uint4*)&P.outHi[z][off] = uh;
                *(uint4*)&P.outLo[z][off] = ul;
            } else {
                float* dst = &P.outF[0][(size_t)grow * N + col];
                *(float4*)dst       = make_float4(vv[0], vv[1], vv[2], vv[3]);
                *(float4*)(dst + 4) = make_float4(vv[4], vv[5], vv[6], vv[7]);
            }
            __syncwarp();
        }
}

// ---------------------------------------------------------------------------
// Fused attention: per (bh, 128-row strip). Loop over 16 j-tiles:
//   S = Q K^T (bf16x3 HMMA), s=S/8, s+=R*sin(s+P), e=exp(s);
//   write e (fp16) to strip buffer; rowsum += e; O += e*V (bf16x3 HMMA).
// Then: scale O by 1/Z -> ctx hi/lo; re-read e strip -> normalized fp32 attn.
// smem: Q,K,V hi/lo tiles + P hi/lo half + fp32 stage = 182272 B dynamic.
// ---------------------------------------------------------------------------
#define QT  (128*LDK)   // 9216 bf16 elems per tile
#define FUSED_SMEM (8*QT*2 + 128*STG*4)   // 147456 + 34816 = 182272

__global__ void __launch_bounds__(256)
attn_fused(const __nv_bfloat16* __restrict__ qhi, const __nv_bfloat16* __restrict__ qlo,
           const __nv_bfloat16* __restrict__ khi, const __nv_bfloat16* __restrict__ klo,
           const __nv_bfloat16* __restrict__ vhi, const __nv_bfloat16* __restrict__ vlo,
           const float* __restrict__ res, const float* __restrict__ ph,
           __half* __restrict__ ebuf, float* __restrict__ attn,
           __nv_bfloat16* __restrict__ ctxhi, __nv_bfloat16* __restrict__ ctxlo)
{
    extern __shared__ __align__(16) __nv_bfloat16 smf[];
    __nv_bfloat16* sQhi = smf + 0*QT;
    __nv_bfloat16* sQlo = smf + 1*QT;
    __nv_bfloat16* sKhi = smf + 2*QT;
    __nv_bfloat16* sKlo = smf + 3*QT;
    __nv_bfloat16* sVhi = smf + 4*QT;
    __nv_bfloat16* sVlo = smf + 5*QT;
    __nv_bfloat16* sPhi = smf + 6*QT;
    __nv_bfloat16* sPlo = smf + 7*QT;
    float* stage = (float*)(smf + 8*QT);
    __shared__ float rowsum[128];
    __shared__ float invZ[128];

    const int bh = blockIdx.y;
    const int b  = bh >> 4;
    const int hh = bh & 15;
    const int i0 = blockIdx.x * 128;
    const int tid = threadIdx.x;
    const int wid = tid >> 5;
    const int lane = tid & 31;
    const int wr = wid & 3;     // EV warp row group
    const int wc = wid >> 2;    // EV warp col group

    const size_t hbase = (size_t)bh * SEQ * HD;
    const float R  = res[hh];
    const float Pp = ph[hh];

    if (tid < 128) rowsum[tid] = 0.f;

    // Q strip load (group: Q)
#pragma unroll
    for (int t = 0; t < 4; t++) {
        int chunk = tid + t * 256;
        int row  = chunk >> 3;
        int co   = (chunk & 7) * 8;
        cp16(sQhi + row * LDK + co, qhi + hbase + (size_t)(i0 + row) * HD + co);
        cp16(sQlo + row * LDK + co, qlo + hbase + (size_t)(i0 + row) * HD + co);
    }
    cp_commit();

    wmma::fragment<wmma::accumulator, 16, 16, 16, float> accO[2][2];
#pragma unroll
    for (int i = 0; i < 2; i++)
#pragma unroll
        for (int j = 0; j < 2; j++) wmma::fill_fragment(accO[i][j], 0.f);

    for (int jt = 0; jt < 16; jt++) {
        __syncthreads();   // protect sK/sV from previous EV reads
        const int j0 = jt * 128;
        // K tile (group), V tile (group)
#pragma unroll
        for (int t = 0; t < 4; t++) {
            int chunk = tid + t * 256;
            int row  = chunk >> 3;
            int co   = (chunk & 7) * 8;
            cp16(sKhi + row * LDK + co, khi + hbase + (size_t)(j0 + row) * HD + co);
            cp16(sKlo + row * LDK + co, klo + hbase + (size_t)(j0 + row) * HD + co);
        }
        cp_commit();
#pragma unroll
        for (int t = 0; t < 4; t++) {
            int chunk = tid + t * 256;
            int row  = chunk >> 3;
            int co   = (chunk & 7) * 8;
            cp16(sVhi + row * LDK + co, vhi + hbase + (size_t)(j0 + row) * HD + co);
            cp16(sVlo + row * LDK + co, vlo + hbase + (size_t)(j0 + row) * HD + co);
        }
        cp_commit();
        asm volatile("cp.async.wait_group 1;");   // K (and Q on first iter) ready
        __syncthreads();

        // process S in column halves (64 cols each)
#pragma unroll
        for (int h = 0; h < 2; h++) {
            wmma::fragment<wmma::accumulator, 16, 16, 16, float> accS[4];
#pragma unroll
            for (int j = 0; j < 4; j++) wmma::fill_fragment(accS[j], 0.f);

            // QK^T: warp = rows wid*16..+16, cols h*64..+64
#pragma unroll
            for (int kk = 0; kk < 64; kk += 16) {
                wmma::fragment<wmma::matrix_a, 16, 16, 16, __nv_bfloat16, wmma::row_major> aH, aL;
                wmma::load_matrix_sync(aH, &sQhi[(wid * 16) * LDK + kk], LDK);
                wmma::load_matrix_sync(aL, &sQlo[(wid * 16) * LDK + kk], LDK);
#pragma unroll
                for (int j = 0; j < 4; j++) {
                    wmma::fragment<wmma::matrix_b, 16, 16, 16, __nv_bfloat16, wmma::col_major> bH, bL;
                    wmma::load_matrix_sync(bH, &sKhi[(h * 64 + j * 16) * LDK + kk], LDK);
                    wmma::load_matrix_sync(bL, &sKlo[(h * 64 + j * 16) * LDK + kk], LDK);
                    wmma::mma_sync(accS[j], aH, bH, accS[j]);
                    wmma::mma_sync(accS[j], aH, bL, accS[j]);
                    wmma::mma_sync(accS[j], aL, bH, accS[j]);
                }
            }
            // modulate + exp
#pragma unroll
            for (int j = 0; j < 4; j++)
#pragma unroll
                for (int e = 0; e < accS[j].num_elements; e++) {
                    float s = accS[j].x[e] * 0.125f;
                    s += R * __sinf(s + Pp);
                    accS[j].x[e] = __expf(s);
                }

            __syncthreads();   // previous half's EV done reading sPhi/sPlo
#pragma unroll
            for (int j = 0; j < 4; j++)
                wmma::store_matrix_sync(&stage[(size_t)(wid * 16) * STG + j * 16],
                                        accS[j], STG, wmma::mem_row_major);
            __syncthreads();

            // scalar phase: rowsum, e fp16 out, P hi/lo split
            {
                int row = tid >> 1;
                int c0  = (tid & 1) * 32;
                float s = 0.f;
                __half* erow = ebuf + ((size_t)bh * SEQ + i0 + row) * SEQ + j0 + h * 64 + c0;
#pragma unroll
                for (int c = 0; c < 32; c += 8) {
                    float4 v0 = *(const float4*)&stage[(size_t)row * STG + c0 + c];
                    float4 v1 = *(const float4*)&stage[(size_t)row * STG + c0 + c + 4];
                    s += v0.x + v0.y + v0.z + v0.w + v1.x + v1.y + v1.z + v1.w;
                    __half2 e0 = __floats2half2_rn(v0.x, v0.y);
                    __half2 e1 = __floats2half2_rn(v0.z, v0.w);
                    __half2 e2 = __floats2half2_rn(v1.x, v1.y);
                    __half2 e3 = __floats2half2_rn(v1.z, v1.w);
                    *(uint4*)&erow[c] = make_uint4(*(uint32_t*)&e0, *(uint32_t*)&e1,
                                                   *(uint32_t*)&e2, *(uint32_t*)&e3);
                    __nv_bfloat16 b0 = __float2bfloat16(v0.x), b1 = __float2bfloat16(v0.y);
                    __nv_bfloat16 b2 = __float2bfloat16(v0.z), b3 = __float2bfloat16(v0.w);
                    __nv_bfloat16 b4 = __float2bfloat16(v1.x), b5 = __float2bfloat16(v1.y);
                    __nv_bfloat16 b6 = __float2bfloat16(v1.z), b7 = __float2bfloat16(v1.w);
                    __nv_bfloat162 q0(b0,b1), q1(b2,b3), q2(b4,b5), q3(b6,b7);
                    *(uint4*)&sPhi[row * LDK + c0 + c] =
                        make_uint4(*(uint32_t*)&q0, *(uint32_t*)&q1, *(uint32_t*)&q2, *(uint32_t*)&q3);
                    *(uint4*)&sPlo[row * LDK + c0 + c] =
                        make_uint4(bfpack(v0.x-__bfloat162float(b0), v0.y-__bfloat162float(b1)),
                                   bfpack(v0.z-__bfloat162float(b2), v0.w-__bfloat162float(b3)),
                                   bfpack(v1.x-__bfloat162float(b4), v1.y-__bfloat162float(b5)),
                                   bfpack(v1.z-__bfloat162float(b6), v1.w-__bfloat162float(b7)));
                }
                s += __shfl_xor_sync(0xffffffffu, s, 1);
                if ((tid & 1) == 0) rowsum[row] += s;
            }
            if (h == 0) asm volatile("cp.async.wait_group 0;");  // V ready
            __syncthreads();

            // O += P_half @ V_half   (P: 128x64, V rows h*64..+64)
#pragma unroll
            for (int kk = 0; kk < 64; kk += 16) {
                wmma::fragment<wmma::matrix_a, 16, 16, 16, __nv_bfloat16, wmma::row_major> aH[2], aL[2];
#pragma unroll
                for (int i = 0; i < 2; i++) {
                    wmma::load_matrix_sync(aH[i], &sPhi[(wr * 32 + i * 16) * LDK + kk], LDK);
                    wmma::load_matrix_sync(aL[i], &sPlo[(wr * 32 + i * 16) * LDK + kk], LDK);
                }
#pragma unroll
                for (int j = 0; j < 2; j++) {
                    wmma::fragment<wmma::matrix_b, 16, 16, 16, __nv_bfloat16, wmma::row_major> bH, bL;
                    wmma::load_matrix_sync(bH, &sVhi[(h * 64 + kk) * LDK + wc * 32 + j * 16], LDK);
                    wmma::load_matrix_sync(bL, &sVlo[(h * 64 + kk) * LDK + wc * 32 + j * 16], LDK);
#pragma unroll
                    for (int i = 0; i < 2; i++) {
                        wmma::mma_sync(accO[i][j], aH[i], bH, accO[i][j]);
                        wmma::mma_sync(accO[i][j], aH[i], bL, accO[i][j]);
                        wmma::mma_sync(accO[i][j], aL[i], bH, accO[i][j]);
                    }
                }
            }
        }
    }

    __syncthreads();
    if (tid < 128) invZ[tid] = 1.f / rowsum[tid];
    __syncthreads();

    // O epilogue: scale by invZ, write ctx bf16 hi/lo
    {
        float* ws = stage + wid * 16 * 20;
        const int er = lane >> 1;
        const int ec = (lane & 1) * 8;
#pragma unroll
        for (int i = 0; i < 2; i++)
#pragma unroll
            for (int j = 0; j < 2; j++) {
                wmma::store_matrix_sync(ws, accO[i][j], 20, wmma::mem_row_major);
                __syncwarp();
                int rl  = wr * 32 + i * 16 + er;
                int col = wc * 32 + j * 16 + ec;
                float iz = invZ[rl];
                size_t off = ((size_t)b * SEQ + i0 + rl) * DM + hh * HD + col;
                float vv[8];
#pragma unroll
                for (int e = 0; e < 8; e++) vv[e] = ws[er * 20 + ec + e] * iz;
                __nv_bfloat16 hb[8];
#pragma unroll
                for (int e = 0; e < 8; e++) hb[e] = __float2bfloat16(vv[e]);
                __nv_bfloat162 p0(hb[0],hb[1]), p1(hb[2],hb[3]), p2(hb[4],hb[5]), p3(hb[6],hb[7]);
                *(uint4*)&ctxhi[off] = make_uint4(*(uint32_t*)&p0, *(uint32_t*)&p1,
                                                  *(uint32_t*)&p2, *(uint32_t*)&p3);
                uint4 ul;
                ul.x = bfpack(vv[0]-__bfloat162float(hb[0]), vv[1]-__bfloat162float(hb[1]));
                ul.y = bfpack(vv[2]-__bfloat162float(hb[2]), vv[3]-__bfloat162float(hb[3]));
                ul.z = bfpack(vv[4]-__bfloat162float(hb[4]), vv[5]-__bfloat162float(hb[5]));
                ul.w = bfpack(vv[6]-__bfloat162float(hb[6]), vv[7]-__bfloat162float(hb[7]));
                *(uint4*)&ctxlo[off] = ul;
                __syncwarp();
            }
    }

    // attn finalize: read own e strip (L2-hot), scale, write fp32
    const __half* estrip = ebuf + ((size_t)bh * SEQ + i0) * SEQ;
    float* astrip = attn + ((size_t)bh * SEQ + i0) * SEQ;
#pragma unroll 4
    for (int t = 0; t < 128; t++) {
        int idx = tid + t * 256;          // 0..32767
        int row = idx >> 8;
        int cc  = (idx & 255) * 8;
        uint4 raw = __ldcg((const uint4*)&estrip[(size_t)row * SEQ + cc]);
        float iz = invZ[row];
        __half2 h0 = *(__half2*)&raw.x, h1 = *(__half2*)&raw.y;
        __half2 h2 = *(__half2*)&raw.z, h3 = *(__half2*)&raw.w;
        float2 f0 = __half22float2(h0), f1 = __half22float2(h1);
        float2 f2 = __half22float2(h2), f3 = __half22float2(h3);
        float4 o0 = {f0.x * iz, f0.y * iz, f1.x * iz, f1.y * iz};
        float4 o1 = {f2.x * iz, f2.y * iz, f3.x * iz, f3.y * iz};
        *(float4*)&astrip[(size_t)row * SEQ + cc]     = o0;
        *(float4*)&astrip[(size_t)row * SEQ + cc + 4] = o1;
    }
}

// ---------------------------------------------------------------------------
// Launch
// ---------------------------------------------------------------------------
extern "C" void kernel_launch(void* const* d_in, const int* in_sizes, int n_in,
                              void* d_out, int out_size)
{
    const float* query = (const float*)d_in[0];
    const float* key   = (const float*)d_in[1];
    const float* value = (const float*)d_in[2];
    const float* Wq    = (const float*)d_in[3];
    const float* bq    = (const float*)d_in[4];
    const float* Wk    = (const float*)d_in[5];
    const float* bk    = (const float*)d_in[6];
    const float* Wv    = (const float*)d_in[7];
    const float* bv    = (const float*)d_in[8];
    const float* Wo    = (const float*)d_in[9];
    const float* bo    = (const float*)d_in[10];
    const float* reso  = (const float*)d_in[11];
    const float* phas  = (const float*)d_in[12];

    __nv_bfloat16 *xqh,*xql,*xkh,*xkl,*xvh,*xvl, *wqh,*wql,*wkh,*wkl,*wvh,*wvl,*woh,*wol;
    __nv_bfloat16 *qh,*ql,*kh,*kl,*vh,*vl, *cxh,*cxl;
    float *zpad, *scratch;
    __half* eb;
    cudaGetSymbolAddress((void**)&xqh, g_xq_hi); cudaGetSymbolAddress((void**)&xql, g_xq_lo);
    cudaGetSymbolAddress((void**)&xkh, g_xk_hi); cudaGetSymbolAddress((void**)&xkl, g_xk_lo);
    cudaGetSymbolAddress((void**)&xvh, g_xv_hi); cudaGetSymbolAddress((void**)&xvl, g_xv_lo);
    cudaGetSymbolAddress((void**)&wqh, g_wq_hi); cudaGetSymbolAddress((void**)&wql, g_wq_lo);
    cudaGetSymbolAddress((void**)&wkh, g_wk_hi); cudaGetSymbolAddress((void**)&wkl, g_wk_lo);
    cudaGetSymbolAddress((void**)&wvh, g_wv_hi); cudaGetSymbolAddress((void**)&wvl, g_wv_lo);
    cudaGetSymbolAddress((void**)&woh, g_wo_hi); cudaGetSymbolAddress((void**)&wol, g_wo_lo);
    cudaGetSymbolAddress((void**)&qh,  g_q_hi);  cudaGetSymbolAddress((void**)&ql,  g_q_lo);
    cudaGetSymbolAddress((void**)&kh,  g_k_hi);  cudaGetSymbolAddress((void**)&kl,  g_k_lo);
    cudaGetSymbolAddress((void**)&vh,  g_v_hi);  cudaGetSymbolAddress((void**)&vl,  g_v_lo);
    cudaGetSymbolAddress((void**)&cxh, g_ctx_hi); cudaGetSymbolAddress((void**)&cxl, g_ctx_lo);
    cudaGetSymbolAddress((void**)&eb,  g_e);
    cudaGetSymbolAddress((void**)&scratch, g_attn_scratch);
    (void)zpad;

    float* out_ptr = (float*)d_out;
    const bool attn_in_out = ((size_t)out_size >= OUT_ELEMS + ATTN_ELEMS);
    float* attn_ptr = attn_in_out ? (out_ptr + OUT_ELEMS) : scratch;

    const int GEMM_SMEM = 2 * GSTAGE * 2;
    cudaFuncSetAttribute(gemm_bf16<0>, cudaFuncAttributeMaxDynamicSharedMemorySize, GEMM_SMEM);
    cudaFuncSetAttribute(gemm_bf16<1>, cudaFuncAttributeMaxDynamicSharedMemorySize, GEMM_SMEM);
    cudaFuncSetAttribute(attn_fused,   cudaFuncAttributeMaxDynamicSharedMemorySize, FUSED_SMEM);

    // 0) split fp32 -> bf16 hi/lo
    const int NX4 = MTOT * DM / 4, NW4 = DM * DM / 4;
    convert_split<<<NX4 / 256, 256>>>((const float4*)query, (uint2*)xqh, (uint2*)xql, NX4);
    convert_split<<<NX4 / 256, 256>>>((const float4*)key,   (uint2*)xkh, (uint2*)xkl, NX4);
    convert_split<<<NX4 / 256, 256>>>((const float4*)value, (uint2*)xvh, (uint2*)xvl, NX4);
    convert_split<<<NW4 / 256, 256>>>((const float4*)Wq,    (uint2*)wqh, (uint2*)wql, NW4);
    convert_split<<<NW4 / 256, 256>>>((const float4*)Wk,    (uint2*)wkh, (uint2*)wkl, NW4);
    convert_split<<<NW4 / 256, 256>>>((const float4*)Wv,    (uint2*)wvh, (uint2*)wvl, NW4);
    convert_split<<<NW4 / 256, 256>>>((const float4*)Wo,    (uint2*)woh, (uint2*)wol, NW4);

    // 1) QKV projections -> bf16 hi/lo head layout
    GemmPtrs Pq = {};
    Pq.Ahi[0]=xqh; Pq.Alo[0]=xql; Pq.Whi[0]=wqh; Pq.Wlo[0]=wql; Pq.bias[0]=bq;
    Pq.outHi[0]=qh; Pq.outLo[0]=ql;
    Pq.Ahi[1]=xkh; Pq.Alo[1]=xkl; Pq.Whi[1]=wkh; Pq.Wlo[1]=wkl; Pq.bias[1]=bk;
    Pq.outHi[1]=kh; Pq.outLo[1]=kl;
    Pq.Ahi[2]=xvh; Pq.Alo[2]=xvl; Pq.Whi[2]=wvh; Pq.Wlo[2]=wvl; Pq.bias[2]=bv;
    Pq.outHi[2]=vh; Pq.outLo[2]=vl;
    dim3 gP(DM / 128, MTOT / 128, 3);
    gemm_bf16<0><<<gP, 256, GEMM_SMEM>>>(Pq, MTOT, DM, DM);

    // 2) Fused scores + softmax + PV + attn write
    dim3 gF(SEQ / 128, BATCH * NH);
    attn_fused<<<gF, 256, FUSED_SMEM>>>(qh, ql, kh, kl, vh, vl, reso, phas,
                                        eb, attn_ptr, cxh, cxl);

    // 3) Output projection -> d_out
    GemmPtrs Po = {};
    Po.Ahi[0]=cxh; Po.Alo[0]=cxl; Po.Whi[0]=woh; Po.Wlo[0]=wol; Po.bias[0]=bo;
    Po.outF[0]=out_ptr;
    dim3 gO(DM / 128, MTOT / 128, 1);
    gemm_bf16<1><<<gO, 256, GEMM_SMEM>>>(Po, MTOT, DM, DM);
}

// round 8
// speedup vs baseline: 1.2456x; 1.2456x over previous
#include <cuda_runtime.h>
#include <cuda_bf16.h>
#include <cuda_fp16.h>
#include <mma.h>
#include <math.h>
#include <stdint.h>

using namespace nvcuda;

#define BATCH 2
#define SEQ   2048
#define DM    1024
#define NH    16
#define HD    64
#define MTOT  (BATCH*SEQ)
#define JT    (SEQ/128)
#define KC    64
#define LDK   72
#define STG_LD 136

static const size_t OUT_ELEMS  = (size_t)BATCH * SEQ * DM;
static const size_t ATTN_ELEMS = (size_t)BATCH * NH * SEQ * SEQ;

// ---------------------------------------------------------------------------
// Device scratch
// ---------------------------------------------------------------------------
__device__ __nv_bfloat16 g_xq_hi[MTOT*DM], g_xq_lo[MTOT*DM];
__device__ __nv_bfloat16 g_xk_hi[MTOT*DM], g_xk_lo[MTOT*DM];
__device__ __nv_bfloat16 g_xv_hi[MTOT*DM], g_xv_lo[MTOT*DM];
__device__ __nv_bfloat16 g_wq_hi[DM*DM], g_wq_lo[DM*DM];
__device__ __nv_bfloat16 g_wk_hi[DM*DM], g_wk_lo[DM*DM];
__device__ __nv_bfloat16 g_wv_hi[DM*DM], g_wv_lo[DM*DM];
__device__ __nv_bfloat16 g_wo_hi[DM*DM], g_wo_lo[DM*DM];
__device__ __nv_bfloat16 g_q_hi[BATCH*NH*SEQ*HD], g_q_lo[BATCH*NH*SEQ*HD];
__device__ __nv_bfloat16 g_k_hi[BATCH*NH*SEQ*HD], g_k_lo[BATCH*NH*SEQ*HD];
__device__ __nv_bfloat16 g_v_hi[BATCH*NH*SEQ*HD], g_v_lo[BATCH*NH*SEQ*HD];
__device__ __nv_bfloat16 g_ctx_hi[MTOT*DM], g_ctx_lo[MTOT*DM];
__device__ __half g_e[(size_t)BATCH*NH*SEQ*SEQ];
__device__ float g_zpart[(size_t)BATCH*NH*JT*SEQ];
__device__ float g_attn_scratch[(size_t)BATCH*NH*SEQ*SEQ];

// ---------------------------------------------------------------------------
// Helpers
// ---------------------------------------------------------------------------
__device__ __forceinline__ void cp16(void* dst, const void* src) {
    asm volatile("cp.async.cg.shared.global [%0], [%1], 16;"
                 :: "r"((uint32_t)__cvta_generic_to_shared(dst)), "l"(src));
}
__device__ __forceinline__ void cp_commit() {
    asm volatile("cp.async.commit_group;");
}
__device__ __forceinline__ uint32_t bfpack(float a, float b) {
    __nv_bfloat162 t(__float2bfloat16(a), __float2bfloat16(b));
    return *(uint32_t*)&t;
}

// batched fp32 -> bf16 hi/lo split: grid.z selects tensor
struct ConvPtrs { const float4* src[7]; uint2* hi[7]; uint2* lo[7]; int n4[7]; };

__global__ void __launch_bounds__(256)
convert_split_b(ConvPtrs C)
{
    int z = blockIdx.z;
    int i = blockIdx.x * 256 + threadIdx.x;
    if (i >= C.n4[z]) return;
    float4 v = C.src[z][i];
    __nv_bfloat16 hx = __float2bfloat16(v.x), hy = __float2bfloat16(v.y);
    __nv_bfloat16 hz = __float2bfloat16(v.z), hw = __float2bfloat16(v.w);
    __nv_bfloat162 h01(hx, hy), h23(hz, hw);
    C.hi[z][i] = make_uint2(*(uint32_t*)&h01, *(uint32_t*)&h23);
    C.lo[z][i] = make_uint2(bfpack(v.x - __bfloat162float(hx), v.y - __bfloat162float(hy)),
                            bfpack(v.z - __bfloat162float(hz), v.w - __bfloat162float(hw)));
}

// ---------------------------------------------------------------------------
// HMMA GEMM (R6-proven)
// ---------------------------------------------------------------------------
struct GemmPtrs {
    const __nv_bfloat16 *Ahi[3], *Alo[3], *Whi[3], *Wlo[3];
    const float* bias[3];
    float* outF[3];
    __nv_bfloat16 *outHi[3], *outLo[3];
};

#define GTILE (128*LDK)
#define GSTAGE (4*GTILE)

template<int MODE>
__global__ void __launch_bounds__(256)
gemm_bf16(GemmPtrs P, int M, int N, int K)
{
    extern __shared__ __align__(16) __nv_bfloat16 sm[];
    const int z = (MODE == 0) ? blockIdx.z : 0;
    const __nv_bfloat16* Ahi = P.Ahi[z];
    const __nv_bfloat16* Alo = P.Alo[z];
    const __nv_bfloat16* Whi = P.Whi[z];
    const __nv_bfloat16* Wlo = P.Wlo[z];
    const float* bias = P.bias[z];

    const int tid = threadIdx.x;
    const int wid = tid >> 5;
    const int lane = tid & 31;
    const int wr = wid & 3;
    const int wc = wid >> 2;
    const int m0 = blockIdx.y * 128;
    const int n0 = blockIdx.x * 128;

    wmma::fragment<wmma::accumulator, 16, 16, 16, float> acc[2][4];
#pragma unroll
    for (int i = 0; i < 2; i++)
#pragma unroll
        for (int j = 0; j < 4; j++) wmma::fill_fragment(acc[i][j], 0.f);

    const int NC = K / KC;

    auto stage_copy = [&](int c, int s) {
        const int k0 = c * KC;
        __nv_bfloat16* base = sm + s * GSTAGE;
#pragma unroll
        for (int t = 0; t < 4; t++) {
            int chunk = tid + t * 256;
            int row  = chunk >> 3;
            int coff = (chunk & 7) * 8;
            cp16(base + 0*GTILE + row * LDK + coff, Ahi + (size_t)(m0 + row) * K + k0 + coff);
            cp16(base + 1*GTILE + row * LDK + coff, Alo + (size_t)(m0 + row) * K + k0 + coff);
            cp16(base + 2*GTILE + row * LDK + coff, Whi + (size_t)(n0 + row) * K + k0 + coff);
            cp16(base + 3*GTILE + row * LDK + coff, Wlo + (size_t)(n0 + row) * K + k0 + coff);
        }
        cp_commit();
    };

    stage_copy(0, 0);

    for (int c = 0; c < NC; c++) {
        if (c + 1 < NC) stage_copy(c + 1, (c + 1) & 1);
        if (c + 1 < NC) asm volatile("cp.async.wait_group 1;");
        else            asm volatile("cp.async.wait_group 0;");
        __syncthreads();

        const __nv_bfloat16* base = sm + (c & 1) * GSTAGE;
        const __nv_bfloat16* sAhi = base + 0*GTILE;
        const __nv_bfloat16* sAlo = base + 1*GTILE;
        const __nv_bfloat16* sWhi = base + 2*GTILE;
        const __nv_bfloat16* sWlo = base + 3*GTILE;

#pragma unroll
        for (int kk = 0; kk < KC; kk += 16) {
            wmma::fragment<wmma::matrix_a, 16, 16, 16, __nv_bfloat16, wmma::row_major> aHi[2], aLo[2];
            wmma::fragment<wmma::matrix_b, 16, 16, 16, __nv_bfloat16, wmma::col_major> bHi[4], bLo[4];
#pragma unroll
            for (int i = 0; i < 2; i++) {
                wmma::load_matrix_sync(aHi[i], &sAhi[(wr * 32 + i * 16) * LDK + kk], LDK);
                wmma::load_matrix_sync(aLo[i], &sAlo[(wr * 32 + i * 16) * LDK + kk], LDK);
            }
#pragma unroll
            for (int j = 0; j < 4; j++) {
                wmma::load_matrix_sync(bHi[j], &sWhi[(wc * 64 + j * 16) * LDK + kk], LDK);
                wmma::load_matrix_sync(bLo[j], &sWlo[(wc * 64 + j * 16) * LDK + kk], LDK);
            }
#pragma unroll
            for (int i = 0; i < 2; i++)
#pragma unroll
                for (int j = 0; j < 4; j++) {
                    wmma::mma_sync(acc[i][j], aHi[i], bHi[j], acc[i][j]);
                    wmma::mma_sync(acc[i][j], aHi[i], bLo[j], acc[i][j]);
                    wmma::mma_sync(acc[i][j], aLo[i], bHi[j], acc[i][j]);
                }
        }
        __syncthreads();
    }

    float* scratch = (float*)sm;
    float* ws = scratch + wid * 16 * 20;
    const int er = lane >> 1;
    const int ec = (lane & 1) * 8;

#pragma unroll
    for (int i = 0; i < 2; i++)
#pragma unroll
        for (int j = 0; j < 4; j++) {
            wmma::store_matrix_sync(ws, acc[i][j], 20, wmma::mem_row_major);
            __syncwarp();
            int grow = m0 + wr * 32 + i * 16 + er;
            int col  = n0 + wc * 64 + j * 16 + ec;
            float4 b0 = *(const float4*)&bias[col];
            float4 b1 = *(const float4*)&bias[col + 4];
            float vv[8];
#pragma unroll
            for (int e = 0; e < 4; e++) vv[e]     = ws[er * 20 + ec + e]     + (&b0.x)[e];
#pragma unroll
            for (int e = 0; e < 4; e++) vv[e + 4] = ws[er * 20 + ec + 4 + e] + (&b1.x)[e];

            if (MODE == 0) {
                int b  = grow >> 11;
                int s  = grow & (SEQ - 1);
                int hh = col >> 6;
                int dd = col & (HD - 1);
                size_t off = (((size_t)(b * NH + hh)) * SEQ + s) * HD + dd;
                uint4 uh, ul;
                __nv_bfloat16 h[8];
#pragma unroll
                for (int e = 0; e < 8; e++) h[e] = __float2bfloat16(vv[e]);
                __nv_bfloat162 p0(h[0],h[1]), p1(h[2],h[3]), p2(h[4],h[5]), p3(h[6],h[7]);
                uh = make_uint4(*(uint32_t*)&p0, *(uint32_t*)&p1, *(uint32_t*)&p2, *(uint32_t*)&p3);
                ul.x = bfpack(vv[0]-__bfloat162float(h[0]), vv[1]-__bfloat162float(h[1]));
                ul.y = bfpack(vv[2]-__bfloat162float(h[2]), vv[3]-__bfloat162float(h[3]));
                ul.z = bfpack(vv[4]-__bfloat162float(h[4]), vv[5]-__bfloat162float(h[5]));
                ul.w = bfpack(vv[6]-__bfloat162float(h[6]), vv[7]-__bfloat162float(h[7]));
                *(uint4*)&P.outHi[z][off] = uh;
                *(uint4*)&P.outLo[z][off] = ul;
            } else {
                float* dst = &P.outF[0][(size_t)grow * N + col];
                *(float4*)dst       = make_float4(vv[0], vv[1], vv[2], vv[3]);
                *(float4*)(dst + 4) = make_float4(vv[4], vv[5], vv[6], vv[7]);
            }
            __syncwarp();
        }
}

// ---------------------------------------------------------------------------
// Scores on HMMA -> fp16 e buffer + partial row sums
// ---------------------------------------------------------------------------
__global__ void __launch_bounds__(256)
scores_wmma(const __nv_bfloat16* __restrict__ qhi, const __nv_bfloat16* __restrict__ qlo,
            const __nv_bfloat16* __restrict__ khi, const __nv_bfloat16* __restrict__ klo,
            const float* __restrict__ res, const float* __restrict__ ph,
            __half* __restrict__ ebuf, float* __restrict__ zpart)
{
    extern __shared__ __align__(16) __nv_bfloat16 sm2[];
    __nv_bfloat16* sQhi = sm2 + 0*GTILE;
    __nv_bfloat16* sQlo = sm2 + 1*GTILE;
    __nv_bfloat16* sKhi = sm2 + 2*GTILE;
    __nv_bfloat16* sKlo = sm2 + 3*GTILE;
    float* stage = (float*)sm2;

    const int bh = blockIdx.z;
    const int h  = bh & (NH - 1);
    const int i0 = blockIdx.y * 128;
    const int j0 = blockIdx.x * 128;
    const int tid = threadIdx.x;
    const int wid = tid >> 5;
    const int wr = wid & 3;
    const int wc = wid >> 2;

    const size_t qbase = (size_t)bh * SEQ * HD;

#pragma unroll
    for (int t = 0; t < 4; t++) {
        int chunk = tid + t * 256;
        int row  = chunk >> 3;
        int coff = (chunk & 7) * 8;
        cp16(sQhi + row * LDK + coff, qhi + qbase + (size_t)(i0 + row) * HD + coff);
        cp16(sQlo + row * LDK + coff, qlo + qbase + (size_t)(i0 + row) * HD + coff);
        cp16(sKhi + row * LDK + coff, khi + qbase + (size_t)(j0 + row) * HD + coff);
        cp16(sKlo + row * LDK + coff, klo + qbase + (size_t)(j0 + row) * HD + coff);
    }
    cp_commit();
    asm volatile("cp.async.wait_group 0;");
    __syncthreads();

    wmma::fragment<wmma::accumulator, 16, 16, 16, float> acc[2][4];
#pragma unroll
    for (int i = 0; i < 2; i++)
#pragma unroll
        for (int j = 0; j < 4; j++) wmma::fill_fragment(acc[i][j], 0.f);

#pragma unroll
    for (int kk = 0; kk < 64; kk += 16) {
        wmma::fragment<wmma::matrix_a, 16, 16, 16, __nv_bfloat16, wmma::row_major> aHi[2], aLo[2];
        wmma::fragment<wmma::matrix_b, 16, 16, 16, __nv_bfloat16, wmma::col_major> bHi[4], bLo[4];
#pragma unroll
        for (int i = 0; i < 2; i++) {
            wmma::load_matrix_sync(aHi[i], &sQhi[(wr * 32 + i * 16) * LDK + kk], LDK);
            wmma::load_matrix_sync(aLo[i], &sQlo[(wr * 32 + i * 16) * LDK + kk], LDK);
        }
#pragma unroll
        for (int j = 0; j < 4; j++) {
            wmma::load_matrix_sync(bHi[j], &sKhi[(wc * 64 + j * 16) * LDK + kk], LDK);
            wmma::load_matrix_sync(bLo[j], &sKlo[(wc * 64 + j * 16) * LDK + kk], LDK);
        }
#pragma unroll
        for (int i = 0; i < 2; i++)
#pragma unroll
            for (int j = 0; j < 4; j++) {
                wmma::mma_sync(acc[i][j], aHi[i], bHi[j], acc[i][j]);
                wmma::mma_sync(acc[i][j], aHi[i], bLo[j], acc[i][j]);
                wmma::mma_sync(acc[i][j], aLo[i], bHi[j], acc[i][j]);
            }
    }

    const float R = res[h];
    const float Pp = ph[h];
#pragma unroll
    for (int i = 0; i < 2; i++)
#pragma unroll
        for (int j = 0; j < 4; j++)
#pragma unroll
            for (int e = 0; e < acc[i][j].num_elements; e++) {
                float s = acc[i][j].x[e] * 0.125f;
                s += R * __sinf(s + Pp);
                acc[i][j].x[e] = __expf(s);
            }

    __syncthreads();
#pragma unroll
    for (int i = 0; i < 2; i++)
#pragma unroll
        for (int j = 0; j < 4; j++)
            wmma::store_matrix_sync(&stage[(size_t)(wr * 32 + i * 16) * STG_LD + wc * 64 + j * 16],
                                    acc[i][j], STG_LD, wmma::mem_row_major);
    __syncthreads();

    // rowsum + fp16 e write (each thread: one 64-col half-row)
    {
        int row  = tid >> 1;
        int c0   = (tid & 1) * 64;
        float s = 0.f;
        const float* pr = &stage[(size_t)row * STG_LD + c0];
        __half* erow = ebuf + ((size_t)bh * SEQ + i0 + row) * SEQ + j0 + c0;
#pragma unroll
        for (int c = 0; c < 64; c += 8) {
            float4 v0 = *(const float4*)&pr[c];
            float4 v1 = *(const float4*)&pr[c + 4];
            s += v0.x + v0.y + v0.z + v0.w + v1.x + v1.y + v1.z + v1.w;
            __half2 e0 = __floats2half2_rn(v0.x, v0.y);
            __half2 e1 = __floats2half2_rn(v0.z, v0.w);
            __half2 e2 = __floats2half2_rn(v1.x, v1.y);
            __half2 e3 = __floats2half2_rn(v1.z, v1.w);
            *(uint4*)&erow[c] = make_uint4(*(uint32_t*)&e0, *(uint32_t*)&e1,
                                           *(uint32_t*)&e2, *(uint32_t*)&e3);
        }
        s += __shfl_xor_sync(0xffffffffu, s, 1);
        if ((tid & 1) == 0)
            zpart[((size_t)bh * JT + blockIdx.x) * SEQ + i0 + row] = s;
    }
}

// ---------------------------------------------------------------------------
// PV on HMMA: read fp16 e, normalize -> fp32 attn out + bf16 hi/lo smem,
// P@V with bf16x3, ctx out as hi/lo.
// ---------------------------------------------------------------------------
#define PV_SMEM ((2*128*LDK + 2*64*LDK) * 2)

__global__ void __launch_bounds__(256)
pv_wmma(const __half* __restrict__ ebuf, float* __restrict__ attn,
        const __nv_bfloat16* __restrict__ vhi, const __nv_bfloat16* __restrict__ vlo,
        const float* __restrict__ zpart,
        __nv_bfloat16* __restrict__ ctxhi, __nv_bfloat16* __restrict__ ctxlo)
{
    extern __shared__ __align__(16) __nv_bfloat16 smp[];
    __nv_bfloat16* sPhi = smp;
    __nv_bfloat16* sPlo = smp + 128*LDK;
    __nv_bfloat16* sVhi = smp + 2*128*LDK;
    __nv_bfloat16* sVlo = smp + 2*128*LDK + 64*LDK;
    __shared__ float invZ[128];

    const int bh = blockIdx.y;
    const int b  = bh >> 4;
    const int h  = bh & 15;
    const int i0 = blockIdx.x * 128;
    const int tid = threadIdx.x;
    const int wid = tid >> 5;
    const int lane = tid & 31;
    const int wr = wid & 3;
    const int wc = wid >> 2;

    if (tid < 128) {
        float z = 0.f;
#pragma unroll
        for (int jt = 0; jt < JT; jt++)
            z += zpart[((size_t)bh * JT + jt) * SEQ + i0 + tid];
        invZ[tid] = 1.f / z;
    }
    __syncthreads();

    const __half* Eb = ebuf + ((size_t)bh * SEQ + i0) * SEQ;
    float* Ab = attn + ((size_t)bh * SEQ + i0) * SEQ;
    const __nv_bfloat16* Vbh = vhi + (size_t)bh * SEQ * HD;
    const __nv_bfloat16* Vbl = vlo + (size_t)bh * SEQ * HD;

    wmma::fragment<wmma::accumulator, 16, 16, 16, float> acc[2][2];
#pragma unroll
    for (int i = 0; i < 2; i++)
#pragma unroll
        for (int j = 0; j < 2; j++) wmma::fill_fragment(acc[i][j], 0.f);

    for (int k0 = 0; k0 < SEQ; k0 += 64) {
        // V tiles via cp.async
#pragma unroll
        for (int t = 0; t < 2; t++) {
            int slot = tid + t * 256;
            int row  = slot >> 3;
            int co   = (slot & 7) * 8;
            cp16(sVhi + row * LDK + co, Vbh + (size_t)(k0 + row) * HD + co);
            cp16(sVlo + row * LDK + co, Vbl + (size_t)(k0 + row) * HD + co);
        }
        cp_commit();

        // P tile: fp16 e -> *invZ -> fp32 attn out + hi/lo smem
#pragma unroll
        for (int t = 0; t < 4; t++) {
            int slot = tid + t * 256;      // 0..1023
            int row  = slot >> 3;          // 0..127
            int c8   = (slot & 7) * 8;     // 0..56
            float iz = invZ[row];
            uint4 raw = *(const uint4*)&Eb[(size_t)row * SEQ + k0 + c8];
            float2 f0 = __half22float2(*(__half2*)&raw.x);
            float2 f1 = __half22float2(*(__half2*)&raw.y);
            float2 f2 = __half22float2(*(__half2*)&raw.z);
            float2 f3 = __half22float2(*(__half2*)&raw.w);
            float p[8] = {f0.x*iz, f0.y*iz, f1.x*iz, f1.y*iz,
                          f2.x*iz, f2.y*iz, f3.x*iz, f3.y*iz};
            *(float4*)&Ab[(size_t)row * SEQ + k0 + c8]     = make_float4(p[0],p[1],p[2],p[3]);
            *(float4*)&Ab[(size_t)row * SEQ + k0 + c8 + 4] = make_float4(p[4],p[5],p[6],p[7]);
            __nv_bfloat16 hb[8];
#pragma unroll
            for (int e = 0; e < 8; e++) hb[e] = __float2bfloat16(p[e]);
            __nv_bfloat162 q0(hb[0],hb[1]), q1(hb[2],hb[3]), q2(hb[4],hb[5]), q3(hb[6],hb[7]);
            *(uint4*)&sPhi[row * LDK + c8] =
                make_uint4(*(uint32_t*)&q0, *(uint32_t*)&q1, *(uint32_t*)&q2, *(uint32_t*)&q3);
            *(uint4*)&sPlo[row * LDK + c8] =
                make_uint4(bfpack(p[0]-__bfloat162float(hb[0]), p[1]-__bfloat162float(hb[1])),
                           bfpack(p[2]-__bfloat162float(hb[2]), p[3]-__bfloat162float(hb[3])),
                           bfpack(p[4]-__bfloat162float(hb[4]), p[5]-__bfloat162float(hb[5])),
                           bfpack(p[6]-__bfloat162float(hb[6]), p[7]-__bfloat162float(hb[7])));
        }
        asm volatile("cp.async.wait_group 0;");
        __syncthreads();

#pragma unroll
        for (int kk = 0; kk < 64; kk += 16) {
            wmma::fragment<wmma::matrix_a, 16, 16, 16, __nv_bfloat16, wmma::row_major> aHi[2], aLo[2];
            wmma::fragment<wmma::matrix_b, 16, 16, 16, __nv_bfloat16, wmma::row_major> bHi[2], bLo[2];
#pragma unroll
            for (int i = 0; i < 2; i++) {
                wmma::load_matrix_sync(aHi[i], &sPhi[(wr * 32 + i * 16) * LDK + kk], LDK);
                wmma::load_matrix_sync(aLo[i], &sPlo[(wr * 32 + i * 16) * LDK + kk], LDK);
            }
#pragma unroll
            for (int j = 0; j < 2; j++) {
                wmma::load_matrix_sync(bHi[j], &sVhi[kk * LDK + wc * 32 + j * 16], LDK);
                wmma::load_matrix_sync(bLo[j], &sVlo[kk * LDK + wc * 32 + j * 16], LDK);
            }
#pragma unroll
            for (int i = 0; i < 2; i++)
#pragma unroll
                for (int j = 0; j < 2; j++) {
                    wmma::mma_sync(acc[i][j], aHi[i], bHi[j], acc[i][j]);
                    wmma::mma_sync(acc[i][j], aHi[i], bLo[j], acc[i][j]);
                    wmma::mma_sync(acc[i][j], aLo[i], bHi[j], acc[i][j]);
                }
        }
        __syncthreads();
    }

    // Epilogue: ctx hi/lo
    float* scratch = (float*)smp;
    float* ws = scratch + wid * 16 * 20;
    const int er = lane >> 1;
    const int ec = (lane & 1) * 8;

#pragma unroll
    for (int i = 0; i < 2; i++)
#pragma unroll
        for (int j = 0; j < 2; j++) {
            wmma::store_matrix_sync(ws, acc[i][j], 20, wmma::mem_row_major);
            __syncwarp();
            int row = i0 + wr * 32 + i * 16 + er;
            int col = wc * 32 + j * 16 + ec;
            size_t off = ((size_t)b * SEQ + row) * DM + h * HD + col;
            float vv[8];
#pragma unroll
            for (int e = 0; e < 8; e++) vv[e] = ws[er * 20 + ec + e];
            __nv_bfloat16 hh[8];
#pragma unroll
            for (int e = 0; e < 8; e++) hh[e] = __float2bfloat16(vv[e]);
            __nv_bfloat162 p0(hh[0],hh[1]), p1(hh[2],hh[3]), p2(hh[4],hh[5]), p3(hh[6],hh[7]);
            *(uint4*)&ctxhi[off] = make_uint4(*(uint32_t*)&p0, *(uint32_t*)&p1,
                                              *(uint32_t*)&p2, *(uint32_t*)&p3);
            uint4 ul;
            ul.x = bfpack(vv[0]-__bfloat162float(hh[0]), vv[1]-__bfloat162float(hh[1]));
            ul.y = bfpack(vv[2]-__bfloat162float(hh[2]), vv[3]-__bfloat162float(hh[3]));
            ul.z = bfpack(vv[4]-__bfloat162float(hh[4]), vv[5]-__bfloat162float(hh[5]));
            ul.w = bfpack(vv[6]-__bfloat162float(hh[6]), vv[7]-__bfloat162float(hh[7]));
            *(uint4*)&ctxlo[off] = ul;
            __syncwarp();
        }
}

// ---------------------------------------------------------------------------
// Launch
// ---------------------------------------------------------------------------
extern "C" void kernel_launch(void* const* d_in, const int* in_sizes, int n_in,
                              void* d_out, int out_size)
{
    const float* query = (const float*)d_in[0];
    const float* key   = (const float*)d_in[1];
    const float* value = (const float*)d_in[2];
    const float* Wq    = (const float*)d_in[3];
    const float* bq    = (const float*)d_in[4];
    const float* Wk    = (const float*)d_in[5];
    const float* bk    = (const float*)d_in[6];
    const float* Wv    = (const float*)d_in[7];
    const float* bv    = (const float*)d_in[8];
    const float* Wo    = (const float*)d_in[9];
    const float* bo    = (const float*)d_in[10];
    const float* reso  = (const float*)d_in[11];
    const float* phas  = (const float*)d_in[12];

    __nv_bfloat16 *xqh,*xql,*xkh,*xkl,*xvh,*xvl, *wqh,*wql,*wkh,*wkl,*wvh,*wvl,*woh,*wol;
    __nv_bfloat16 *qh,*ql,*kh,*kl,*vh,*vl, *cxh,*cxl;
    float *zp, *scratch;
    __half* eb;
    cudaGetSymbolAddress((void**)&xqh, g_xq_hi); cudaGetSymbolAddress((void**)&xql, g_xq_lo);
    cudaGetSymbolAddress((void**)&xkh, g_xk_hi); cudaGetSymbolAddress((void**)&xkl, g_xk_lo);
    cudaGetSymbolAddress((void**)&xvh, g_xv_hi); cudaGetSymbolAddress((void**)&xvl, g_xv_lo);
    cudaGetSymbolAddress((void**)&wqh, g_wq_hi); cudaGetSymbolAddress((void**)&wql, g_wq_lo);
    cudaGetSymbolAddress((void**)&wkh, g_wk_hi); cudaGetSymbolAddress((void**)&wkl, g_wk_lo);
    cudaGetSymbolAddress((void**)&wvh, g_wv_hi); cudaGetSymbolAddress((void**)&wvl, g_wv_lo);
    cudaGetSymbolAddress((void**)&woh, g_wo_hi); cudaGetSymbolAddress((void**)&wol, g_wo_lo);
    cudaGetSymbolAddress((void**)&qh,  g_q_hi);  cudaGetSymbolAddress((void**)&ql,  g_q_lo);
    cudaGetSymbolAddress((void**)&kh,  g_k_hi);  cudaGetSymbolAddress((void**)&kl,  g_k_lo);
    cudaGetSymbolAddress((void**)&vh,  g_v_hi);  cudaGetSymbolAddress((void**)&vl,  g_v_lo);
    cudaGetSymbolAddress((void**)&cxh, g_ctx_hi); cudaGetSymbolAddress((void**)&cxl, g_ctx_lo);
    cudaGetSymbolAddress((void**)&eb,  g_e);
    cudaGetSymbolAddress((void**)&zp,  g_zpart);
    cudaGetSymbolAddress((void**)&scratch, g_attn_scratch);

    float* out_ptr = (float*)d_out;
    const bool attn_in_out = ((size_t)out_size >= OUT_ELEMS + ATTN_ELEMS);
    float* attn_ptr = attn_in_out ? (out_ptr + OUT_ELEMS) : scratch;

    const int GEMM_SMEM = 2 * GSTAGE * 2;
    const int SCORE_SMEM = GSTAGE * 2;
    cudaFuncSetAttribute(gemm_bf16<0>, cudaFuncAttributeMaxDynamicSharedMemorySize, GEMM_SMEM);
    cudaFuncSetAttribute(gemm_bf16<1>, cudaFuncAttributeMaxDynamicSharedMemorySize, GEMM_SMEM);
    cudaFuncSetAttribute(scores_wmma,  cudaFuncAttributeMaxDynamicSharedMemorySize, SCORE_SMEM);
    cudaFuncSetAttribute(pv_wmma,      cudaFuncAttributeMaxDynamicSharedMemorySize, PV_SMEM);

    // 0) batched split fp32 -> bf16 hi/lo (one launch)
    const int NX4 = MTOT * DM / 4, NW4 = DM * DM / 4;
    ConvPtrs C = {};
    C.src[0]=(const float4*)query; C.hi[0]=(uint2*)xqh; C.lo[0]=(uint2*)xql; C.n4[0]=NX4;
    C.src[1]=(const float4*)key;   C.hi[1]=(uint2*)xkh; C.lo[1]=(uint2*)xkl; C.n4[1]=NX4;
    C.src[2]=(const float4*)value; C.hi[2]=(uint2*)xvh; C.lo[2]=(uint2*)xvl; C.n4[2]=NX4;
    C.src[3]=(const float4*)Wq;    C.hi[3]=(uint2*)wqh; C.lo[3]=(uint2*)wql; C.n4[3]=NW4;
    C.src[4]=(const float4*)Wk;    C.hi[4]=(uint2*)wkh; C.lo[4]=(uint2*)wkl; C.n4[4]=NW4;
    C.src[5]=(const float4*)Wv;    C.hi[5]=(uint2*)wvh; C.lo[5]=(uint2*)wvl; C.n4[5]=NW4;
    C.src[6]=(const float4*)Wo;    C.hi[6]=(uint2*)woh; C.lo[6]=(uint2*)wol; C.n4[6]=NW4;
    dim3 gC((NX4 + 255) / 256, 1, 7);
    convert_split_b<<<gC, 256>>>(C);

    // 1) QKV projections -> bf16 hi/lo head layout
    GemmPtrs Pq = {};
    Pq.Ahi[0]=xqh; Pq.Alo[0]=xql; Pq.Whi[0]=wqh; Pq.Wlo[0]=wql; Pq.bias[0]=bq;
    Pq.outHi[0]=qh; Pq.outLo[0]=ql;
    Pq.Ahi[1]=xkh; Pq.Alo[1]=xkl; Pq.Whi[1]=wkh; Pq.Wlo[1]=wkl; Pq.bias[1]=bk;
    Pq.outHi[1]=kh; Pq.outLo[1]=kl;
    Pq.Ahi[2]=xvh; Pq.Alo[2]=xvl; Pq.Whi[2]=wvh; Pq.Wlo[2]=wvl; Pq.bias[2]=bv;
    Pq.outHi[2]=vh; Pq.outLo[2]=vl;
    dim3 gP(DM / 128, MTOT / 128, 3);
    gemm_bf16<0><<<gP, 256, GEMM_SMEM>>>(Pq, MTOT, DM, DM);

    // 2) Scores -> fp16 e + zpart
    dim3 gS(SEQ / 128, SEQ / 128, BATCH * NH);
    scores_wmma<<<gS, 256, SCORE_SMEM>>>(qh, ql, kh, kl, reso, phas, eb, zp);

    // 3) PV: normalize + attn out + P@V -> ctx hi/lo
    dim3 gV(SEQ / 128, BATCH * NH);
    pv_wmma<<<gV, 256, PV_SMEM>>>(eb, attn_ptr, vh, vl, zp, cxh, cxl);

    // 4) Output projection -> d_out
    GemmPtrs Po = {};
    Po.Ahi[0]=cxh; Po.Alo[0]=cxl; Po.Whi[0]=woh; Po.Wlo[0]=wol; Po.bias[0]=bo;
    Po.outF[0]=out_ptr;
    dim3 gO(DM / 128, MTOT / 128, 1);
    gemm_bf16<1><<<gO, 256, GEMM_SMEM>>>(Po, MTOT, DM, DM);
}